// round 5
// baseline (speedup 1.0000x reference)
#include <cuda_runtime.h>
#include <cuda_fp16.h>

// Problem constants (fixed by dataset)
#define NB    16
#define INCC  32
#define INNX  65536
#define OUTCC 32
#define OUTNX 8192
#define MAXD  16
#define NF    512     // NB*INCC feature columns total
#define NFC   128     // feature columns per chunk (4 batch rows)
#define NCHUNK 4
#define OB    8       // output nodes per CTA (one per warp)

// 64 MB fp16 feature table: feat[inn][j] = x[n,c,inn]*weight[c,inn], j = n*32+c
__device__ __half g_feat_h[(size_t)INNX * NF];

// ---------------------------------------------------------------------------
// Kernel 1: fused scale + transpose + fp32->fp16 for one j-chunk of 128 cols.
// Same proven R3 tile (64 j x 32 inn), j offset by chunk.
// ---------------------------------------------------------------------------
__global__ __launch_bounds__(256) void prep_kernel(const float* __restrict__ x,
                                                   const float* __restrict__ w,
                                                   int j_base) {
    __shared__ float tile[64][33];
    const int inn0 = blockIdx.x << 5;
    const int j0   = j_base + (blockIdx.y << 6);
    const int tx = threadIdx.x, ty = threadIdx.y;   // 32 x 8
    const int inn = inn0 + tx;

#pragma unroll
    for (int r = 0; r < 8; r++) {
        const int jl = ty + (r << 3);
        const int j  = j0 + jl;
        const int c  = j & 31;
        tile[jl][tx] = __ldcs(x + (size_t)j * INNX + inn) * __ldg(w + (size_t)c * INNX + inn);
    }
    __syncthreads();

    __half2* out2 = (__half2*)g_feat_h;   // row stride = 256 half2
    const int tid = (ty << 5) + tx;
#pragma unroll
    for (int k = 0; k < 4; k++) {
        const int e     = tid + (k << 8);
        const int inn_l = e >> 5;          // 0..31
        const int l     = e & 31;          // half2 col within tile
        const float a = tile[2 * l][inn_l];
        const float b = tile[2 * l + 1][inn_l];
        out2[(size_t)(inn0 + inn_l) * 256 + (j0 >> 1) + l] = __floats2half2_rn(a, b);
    }
}

// ---------------------------------------------------------------------------
// Kernel 2: per-chunk fused gather + pool + GEMM + staged transposed store.
// Warp per output node; chunk covers 128 feature cols (4 batch rows).
// Lane loads one uint2 (4 halves) per gathered row -> coalesced 256B/warp.
// ---------------------------------------------------------------------------
__global__ __launch_bounds__(256, 4) void gather_kernel(
    const void*  __restrict__ Araw,
    const float* __restrict__ mask,
    const float* __restrict__ mw,
    const float* __restrict__ ctw,
    const float* __restrict__ ctb,
    const float* __restrict__ bias,
    float* __restrict__ out,
    int chunk)
{
    __shared__ float s_pool[OB][NFC];        // 4 KB
    __shared__ float s_stage[NFC][OB + 1];   // 4.5 KB
    __shared__ int   s_is64;

    const int tid  = threadIdx.x;
    const int w    = tid >> 5;
    const int lane = tid & 31;

    if (tid == 0) {
        const long long* a64 = (const long long*)Araw;
        int is64 = 1;
#pragma unroll
        for (int i = 0; i < 8; i++)
            if ((unsigned long long)a64[i] >= (unsigned long long)INNX) is64 = 0;
        s_is64 = is64;
    }
    __syncthreads();
    const int is64 = s_is64;

    const int o_base = blockIdx.x * OB;
    const int o      = o_base + w;

    int   av = 0;
    float wv = 0.f;
    if (lane < MAXD) {
        av = is64 ? (int)((const long long*)Araw)[(size_t)o * MAXD + lane]
                  : ((const int*)Araw)[(size_t)o * MAXD + lane];
        wv = mw[o * MAXD + lane] * mask[o * MAXD + lane];
    }

    // ---- gather + pool: lane covers cols [4*lane, 4*lane+4) of this chunk ----
    const uint2* feat2 = (const uint2*)g_feat_h;   // full row stride = 128 uint2
    const int    coff  = chunk * 32 + lane;        // uint2 offset within row
    float acc0 = 0.f, acc1 = 0.f, acc2 = 0.f, acc3 = 0.f;

#pragma unroll
    for (int d = 0; d < MAXD; d++) {
        const int   idx = __shfl_sync(0xffffffffu, av, d);
        const float wd  = __shfl_sync(0xffffffffu, wv, d);
        uint2 u = __ldg(feat2 + (size_t)idx * 128 + coff);
        const __half2* h = (const __half2*)&u;
        float2 f0 = __half22float2(h[0]);
        float2 f1 = __half22float2(h[1]);
        acc0 += wd * f0.x;  acc1 += wd * f0.y;
        acc2 += wd * f1.x;  acc3 += wd * f1.y;
    }

    float4* sp4 = (float4*)s_pool[w];
    sp4[lane] = make_float4(acc0, acc1, acc2, acc3);   // contiguous, conflict-free
    __syncwarp();

    // ---- ct_weight row in regs AFTER gather (keeps reg peak low) ----
    float wreg[32];
    {
        const float4* cw4 = (const float4*)(ctw + lane * INCC);
#pragma unroll
        for (int q = 0; q < 8; q++) {
            float4 v = __ldg(cw4 + q);
            wreg[4 * q + 0] = v.x; wreg[4 * q + 1] = v.y;
            wreg[4 * q + 2] = v.z; wreg[4 * q + 3] = v.w;
        }
    }
    const float cb = __ldg(ctb + lane);

    // ---- GEMM: 4 batch rows in this chunk ----
#pragma unroll
    for (int t = 0; t < 4; t++) {
        float y = cb;
#pragma unroll
        for (int c4 = 0; c4 < 8; c4++) {
            float4 p = sp4[t * 8 + c4];       // warp-broadcast LDS.128
            y += p.x * wreg[4 * c4 + 0] + p.y * wreg[4 * c4 + 1]
               + p.z * wreg[4 * c4 + 2] + p.w * wreg[4 * c4 + 3];
        }
        s_stage[t * 32 + lane][w] = y;
    }
    __syncthreads();

    // ---- coalesced write-out of this chunk's 128 output rows ----
#pragma unroll
    for (int e = tid; e < NFC * OB; e += 256) {
        const int row  = e >> 3;                 // OB == 8
        const int col  = e & 7;
        const int g    = chunk * NFC + row;      // global output row
        const int oo   = o_base + col;
        const int dout = g & 31;
        out[(size_t)g * OUTNX + oo] = s_stage[row][col] + __ldg(bias + (size_t)dout * OUTNX + oo);
    }
}

extern "C" void kernel_launch(void* const* d_in, const int* in_sizes, int n_in,
                              void* d_out, int out_size) {
    const float* x    = (const float*)d_in[0];
    const void*  A    = d_in[1];
    const float* w    = (const float*)d_in[2];
    const float* mask = (const float*)d_in[3];
    const float* mw   = (const float*)d_in[4];
    const float* ctw  = (const float*)d_in[5];
    const float* ctb  = (const float*)d_in[6];
    const float* bias = (const float*)d_in[7];
    float* out = (float*)d_out;
    (void)in_sizes; (void)n_in; (void)out_size;

    // Side stream + events for pipelined prep/gather (capture-safe fork/join).
    // Created fresh per call and intentionally not destroyed (a handful of
    // handles over the harness's 2-3 calls; no device memory involved).
    cudaStream_t s2;
    cudaStreamCreateWithFlags(&s2, cudaStreamNonBlocking);
    cudaEvent_t evP[NCHUNK], evJ;
    for (int i = 0; i < NCHUNK; i++)
        cudaEventCreateWithFlags(&evP[i], cudaEventDisableTiming);
    cudaEventCreateWithFlags(&evJ, cudaEventDisableTiming);

    dim3 pgrid(INNX / 32, NFC / 64);
    dim3 pblk(32, 8);

    for (int i = 0; i < NCHUNK; i++) {
        prep_kernel<<<pgrid, pblk>>>(x, w, i * NFC);
        cudaEventRecord(evP[i], 0);
    }
    for (int i = 0; i < NCHUNK; i++) {
        cudaStreamWaitEvent(s2, evP[i], 0);
        gather_kernel<<<OUTNX / OB, 256, 0, s2>>>(A, mask, mw, ctw, ctb, bias, out, i);
    }
    cudaEventRecord(evJ, s2);
    cudaStreamWaitEvent(0, evJ, 0);
}

// round 6
// speedup vs baseline: 1.4022x; 1.4022x over previous
#include <cuda_runtime.h>
#include <cuda_fp16.h>

// Problem constants (fixed by dataset)
#define NB    16
#define INCC  32
#define INNX  65536
#define OUTCC 32
#define OUTNX 8192
#define MAXD  16
#define NF    512     // NB*INCC feature columns
#define OB    8       // output nodes per CTA (one per warp)

// 64 MB fp16 feature table: feat[inn][j] = x[n,c,inn]*weight[c,inn], j = n*32+c
__device__ __half g_feat_h[(size_t)INNX * NF];

// ---------------------------------------------------------------------------
// Kernel 1: fused scale + transpose + fp32->fp16, conflict-free half2 smem.
// Tile = 64 j x 32 inn. Each thread loads a j-pair (2 LDG) x 4 iters (MLP 8),
// converts to half2 before smem. STS stride 33 (distinct banks), LDS with
// lane=jh at half2-stride 33 -> bank = lane (conflict-free). 128B coalesced
// half2 row stores to the table. __ldcs on x keeps L2 for the table.
// ---------------------------------------------------------------------------
__global__ __launch_bounds__(256) void prep_kernel(const float* __restrict__ x,
                                                   const float* __restrict__ w) {
    __shared__ __half2 t2[32][33];
    const int inn0 = blockIdx.x << 5;
    const int j0   = blockIdx.y << 6;
    const int tx = threadIdx.x, ty = threadIdx.y;   // 32 x 8
    const int inn = inn0 + tx;

#pragma unroll
    for (int k = 0; k < 4; k++) {
        const int jh = ty + (k << 3);          // 0..31 (half2 row)
        const int j  = j0 + 2 * jh;
        const int c0 = j & 31;
        const int c1 = (j + 1) & 31;
        const float a = __ldcs(x + (size_t)j * INNX + inn)
                        * __ldg(w + (size_t)c0 * INNX + inn);
        const float b = __ldcs(x + (size_t)(j + 1) * INNX + inn)
                        * __ldg(w + (size_t)c1 * INNX + inn);
        t2[jh][tx] = __floats2half2_rn(a, b);
    }
    __syncthreads();

    __half2* out2 = (__half2*)g_feat_h;   // row stride = 256 half2
    const int tid = (ty << 5) + tx;
#pragma unroll
    for (int k = 0; k < 4; k++) {
        const int e     = tid + (k << 8);
        const int inn_l = e >> 5;          // fixed per warp
        const int jh    = e & 31;          // = lane -> conflict-free LDS
        out2[(size_t)(inn0 + inn_l) * 256 + (j0 >> 1) + jh] = t2[jh][inn_l];
    }
}

// ---------------------------------------------------------------------------
// Kernel 2: FUSED warp-per-output-node gather + pool + register GEMM +
// staged transposed store. Pooled vector kept in a permuted smem layout so
// its stores are 4 coalesced conflict-free STS.128 per lane:
//   p4[b*32 + lane], b=0..3 covering half-cols
//   b=0:[8L,8L+4) b=1:[8L+4,8L+8) b=2:[256+8L,+4) b=3:[256+8L+4,+8)
// GEMM reads it back with uniform broadcast LDS at the inverse index.
// ---------------------------------------------------------------------------
__global__ __launch_bounds__(256, 4) void gather_kernel(
    const void*  __restrict__ Araw,
    const float* __restrict__ mask,
    const float* __restrict__ mw,
    const float* __restrict__ ctw,
    const float* __restrict__ ctb,
    const float* __restrict__ bias,
    float* __restrict__ out)
{
    __shared__ float s_pool[OB][NF];         // permuted pooled (16 KB)
    __shared__ float s_stage[NF][OB + 1];    // output staging (18 KB)
    __shared__ int   s_is64;

    const int tid  = threadIdx.x;
    const int w    = tid >> 5;
    const int lane = tid & 31;

    if (tid == 0) {
        const long long* a64 = (const long long*)Araw;
        int is64 = 1;
#pragma unroll
        for (int i = 0; i < 8; i++)
            if ((unsigned long long)a64[i] >= (unsigned long long)INNX) is64 = 0;
        s_is64 = is64;
    }
    __syncthreads();
    const int is64 = s_is64;

    const int o_base = blockIdx.x * OB;
    const int o      = o_base + w;

    // neighbor indices + pooling weights, distributed in lanes 0..15
    int   av = 0;
    float wv = 0.f;
    if (lane < MAXD) {
        av = is64 ? (int)((const long long*)Araw)[(size_t)o * MAXD + lane]
                  : ((const int*)Araw)[(size_t)o * MAXD + lane];
        wv = mw[o * MAXD + lane] * mask[o * MAXD + lane];
    }

    // ---- gather + pool: lane handles uint4 cols {lane, lane+32} of 64 ----
    const uint4* feat4 = (const uint4*)g_feat_h;   // row stride = 64 uint4
    float acc[16];
#pragma unroll
    for (int i = 0; i < 16; i++) acc[i] = 0.f;

#pragma unroll
    for (int d = 0; d < MAXD; d++) {
        const int   idx = __shfl_sync(0xffffffffu, av, d);
        const float wd  = __shfl_sync(0xffffffffu, wv, d);
        const uint4* row = feat4 + (size_t)idx * 64;
        uint4 u0 = __ldg(row + lane);
        uint4 u1 = __ldg(row + lane + 32);
        const __half2* h0 = (const __half2*)&u0;
        const __half2* h1 = (const __half2*)&u1;
#pragma unroll
        for (int q = 0; q < 4; q++) {
            float2 f0 = __half22float2(h0[q]);
            float2 f1 = __half22float2(h1[q]);
            acc[2 * q + 0]     += wd * f0.x;
            acc[2 * q + 1]     += wd * f0.y;
            acc[8 + 2 * q + 0] += wd * f1.x;
            acc[8 + 2 * q + 1] += wd * f1.y;
        }
    }

    // permuted pooled stores: 4 coalesced conflict-free STS.128
    float4* sp4 = (float4*)s_pool[w];
    sp4[lane]      = make_float4(acc[0],  acc[1],  acc[2],  acc[3]);
    sp4[32 + lane] = make_float4(acc[4],  acc[5],  acc[6],  acc[7]);
    sp4[64 + lane] = make_float4(acc[8],  acc[9],  acc[10], acc[11]);
    sp4[96 + lane] = make_float4(acc[12], acc[13], acc[14], acc[15]);
    __syncwarp();

    // ---- ct_weight row in regs AFTER gather (keeps reg peak low) ----
    float wreg[32];
    {
        const float4* cw4 = (const float4*)(ctw + lane * INCC);
#pragma unroll
        for (int q = 0; q < 8; q++) {
            float4 v = __ldg(cw4 + q);
            wreg[4 * q + 0] = v.x; wreg[4 * q + 1] = v.y;
            wreg[4 * q + 2] = v.z; wreg[4 * q + 3] = v.w;
        }
    }
    const float cb = __ldg(ctb + lane);

    // ---- GEMM: y[n=t][dout=lane] = cb + sum_c pooled[t*32+c]*ctw[lane][c] ----
#pragma unroll
    for (int t = 0; t < NB; t++) {
        float y = cb;
#pragma unroll
        for (int c4 = 0; c4 < 8; c4++) {
            // inverse of the permuted layout for j = t*32 + 4*c4
            const int idx = ((t >> 3) ? 64 : 0) + ((c4 & 1) ? 32 : 0)
                          + 4 * (t & 7) + (c4 >> 1);
            float4 p = sp4[idx];               // uniform warp-broadcast LDS.128
            y += p.x * wreg[4 * c4 + 0] + p.y * wreg[4 * c4 + 1]
               + p.z * wreg[4 * c4 + 2] + p.w * wreg[4 * c4 + 3];
        }
        s_stage[t * 32 + lane][w] = y;
    }
    __syncthreads();

    // ---- coalesced write-out: out[row*8192 + o] = stage + bias ----
#pragma unroll
    for (int e = tid; e < NF * OB; e += 256) {
        const int row  = e >> 3;       // OB == 8
        const int col  = e & 7;
        const int oo   = o_base + col;
        const int dout = row & 31;
        out[(size_t)row * OUTNX + oo] = s_stage[row][col] + __ldg(bias + (size_t)dout * OUTNX + oo);
    }
}

extern "C" void kernel_launch(void* const* d_in, const int* in_sizes, int n_in,
                              void* d_out, int out_size) {
    const float* x    = (const float*)d_in[0];
    const void*  A    = d_in[1];
    const float* w    = (const float*)d_in[2];
    const float* mask = (const float*)d_in[3];
    const float* mw   = (const float*)d_in[4];
    const float* ctw  = (const float*)d_in[5];
    const float* ctb  = (const float*)d_in[6];
    const float* bias = (const float*)d_in[7];
    float* out = (float*)d_out;
    (void)in_sizes; (void)n_in; (void)out_size;

    dim3 pgrid(INNX / 32, NF / 64);
    dim3 pblk(32, 8);
    prep_kernel<<<pgrid, pblk>>>(x, w);

    gather_kernel<<<OUTNX / OB, 256>>>(A, mask, mw, ctw, ctb, bias, out);
}

// round 7
// speedup vs baseline: 1.4167x; 1.0104x over previous
#include <cuda_runtime.h>
#include <cuda_fp16.h>

// Problem constants (fixed by dataset)
#define NB    16
#define INCC  32
#define INNX  65536
#define OUTCC 32
#define OUTNX 8192
#define MAXD  16
#define NF    512     // NB*INCC feature columns
#define OB    8       // output nodes per CTA (one per warp)

// 64 MB fp16 feature table: feat[inn][j] = x[n,c,inn]*weight[c,inn], j = n*32+c
__device__ __half g_feat_h[(size_t)INNX * NF];

// ---- packed f32x2 helpers (sm_103a FFMA2) ----
__device__ __forceinline__ unsigned long long pk2(float lo, float hi) {
    unsigned long long r;
    asm("mov.b64 %0,{%1,%2};" : "=l"(r) : "f"(lo), "f"(hi));
    return r;
}
__device__ __forceinline__ void upk2(unsigned long long v, float& lo, float& hi) {
    asm("mov.b64 {%0,%1},%2;" : "=f"(lo), "=f"(hi) : "l"(v));
}
__device__ __forceinline__ unsigned long long ffma2(unsigned long long a,
                                                    unsigned long long b,
                                                    unsigned long long c) {
    unsigned long long d;
    asm("fma.rn.f32x2 %0,%1,%2,%3;" : "=l"(d) : "l"(a), "l"(b), "l"(c));
    return d;
}

// ---------------------------------------------------------------------------
// Kernel 1: fused scale + transpose + fp32->fp16. Tile = 64 j x 64 inn,
// MLP 16 x-loads/thread, 32-bit indexing, conflict-free half2 smem
// (STS stride 1, LDS bank = lane), 128B coalesced half2 row stores.
// ---------------------------------------------------------------------------
__global__ __launch_bounds__(256) void prep_kernel(const float* __restrict__ x,
                                                   const float* __restrict__ w) {
    __shared__ __half2 t2[32][65];
    const unsigned inn0 = blockIdx.x << 6;
    const unsigned j0   = blockIdx.y << 6;
    const unsigned tx = threadIdx.x, ty = threadIdx.y;   // 32 x 8

#pragma unroll
    for (int k = 0; k < 4; k++) {
        const unsigned jh = ty + (k << 3);          // 0..31 (half2 row)
        const unsigned j  = j0 + 2 * jh;
        const unsigned c0 = j & 31;
        const unsigned c1 = (j + 1) & 31;
        const unsigned bx0 = j * INNX + inn0 + tx;
        const unsigned bw0 = c0 * INNX + inn0 + tx;
        const unsigned bw1 = c1 * INNX + inn0 + tx;
        const float a0 = __ldcs(x + bx0)              * __ldg(w + bw0);
        const float b0 = __ldcs(x + bx0 + INNX)       * __ldg(w + bw1);
        const float a1 = __ldcs(x + bx0 + 32)         * __ldg(w + bw0 + 32);
        const float b1 = __ldcs(x + bx0 + INNX + 32)  * __ldg(w + bw1 + 32);
        t2[jh][tx]      = __floats2half2_rn(a0, b0);
        t2[jh][tx + 32] = __floats2half2_rn(a1, b1);
    }
    __syncthreads();

    __half2* out2 = (__half2*)g_feat_h;   // row stride = 256 half2
    const unsigned tid = (ty << 5) + tx;
#pragma unroll
    for (int k = 0; k < 8; k++) {
        const unsigned e     = tid + (k << 8);
        const unsigned inn_l = e >> 5;          // 0..63, fixed per warp
        const unsigned jh    = e & 31;          // = lane -> conflict-free LDS
        out2[(inn0 + inn_l) * 256u + (j0 >> 1) + jh] = t2[jh][inn_l];
    }
}

// ---------------------------------------------------------------------------
// Kernel 2: FUSED warp-per-output-node gather + HFMA2 pool + FFMA2 GEMM +
// staged transposed store. Pooled vector in permuted smem layout
// (4 coalesced conflict-free STS.128; GEMM reads via uniform broadcast LDS
// at the verified inverse index).
// ---------------------------------------------------------------------------
__global__ __launch_bounds__(256, 4) void gather_kernel(
    const void*  __restrict__ Araw,
    const float* __restrict__ mask,
    const float* __restrict__ mw,
    const float* __restrict__ ctw,
    const float* __restrict__ ctb,
    const float* __restrict__ bias,
    float* __restrict__ out)
{
    __shared__ __align__(16) float s_pool[OB][NF];   // permuted pooled (16 KB)
    __shared__ float s_stage[NF][OB + 1];            // output staging (18 KB)
    __shared__ int   s_is64;

    const int tid  = threadIdx.x;
    const int w    = tid >> 5;
    const int lane = tid & 31;

    if (tid == 0) {
        const long long* a64 = (const long long*)Araw;
        int is64 = 1;
#pragma unroll
        for (int i = 0; i < 8; i++)
            if ((unsigned long long)a64[i] >= (unsigned long long)INNX) is64 = 0;
        s_is64 = is64;
    }
    __syncthreads();
    const int is64 = s_is64;

    const int o_base = blockIdx.x * OB;
    const int o      = o_base + w;

    // neighbor indices + pooling weights, distributed in lanes 0..15
    unsigned av = 0;
    float    wv = 0.f;
    if (lane < MAXD) {
        av = is64 ? (unsigned)((const long long*)Araw)[(size_t)o * MAXD + lane]
                  : (unsigned)((const int*)Araw)[(size_t)o * MAXD + lane];
        wv = mw[o * MAXD + lane] * mask[o * MAXD + lane];
    }

    // ---- gather + pool in half2 (HFMA2): lane covers uint4 cols {lane, lane+32} ----
    const char* fbase = (const char*)g_feat_h;
    __half2 acc[8];
#pragma unroll
    for (int i = 0; i < 8; i++) acc[i] = __float2half2_rn(0.f);

#pragma unroll
    for (int d = 0; d < MAXD; d++) {
        const unsigned idx = __shfl_sync(0xffffffffu, av, d);
        const float    wd  = __shfl_sync(0xffffffffu, wv, d);
        const __half2  wh  = __half2half2(__float2half_rn(wd));
        const unsigned roff = idx * 1024u;     // 1 KB rows, < 64 MB -> 32-bit
        uint4 u0 = __ldg((const uint4*)(fbase + roff + lane * 16));
        uint4 u1 = __ldg((const uint4*)(fbase + roff + 512 + lane * 16));
        const __half2* h0 = (const __half2*)&u0;
        const __half2* h1 = (const __half2*)&u1;
#pragma unroll
        for (int q = 0; q < 4; q++) {
            acc[q]     = __hfma2(h0[q], wh, acc[q]);
            acc[4 + q] = __hfma2(h1[q], wh, acc[4 + q]);
        }
    }

    // permuted pooled stores: 4 coalesced conflict-free STS.128
    float4* sp4 = (float4*)s_pool[w];
    {
        float2 f0 = __half22float2(acc[0]), f1 = __half22float2(acc[1]);
        float2 f2 = __half22float2(acc[2]), f3 = __half22float2(acc[3]);
        float2 f4 = __half22float2(acc[4]), f5 = __half22float2(acc[5]);
        float2 f6 = __half22float2(acc[6]), f7 = __half22float2(acc[7]);
        sp4[lane]      = make_float4(f0.x, f0.y, f1.x, f1.y);
        sp4[32 + lane] = make_float4(f2.x, f2.y, f3.x, f3.y);
        sp4[64 + lane] = make_float4(f4.x, f4.y, f5.x, f5.y);
        sp4[96 + lane] = make_float4(f6.x, f6.y, f7.x, f7.y);
    }
    __syncwarp();

    // ---- ct_weight row packed in f32x2 regs AFTER gather ----
    unsigned long long wp[16];
    {
        const float4* cw4 = (const float4*)(ctw + lane * INCC);
#pragma unroll
        for (int q = 0; q < 8; q++) {
            float4 v = __ldg(cw4 + q);
            wp[2 * q]     = pk2(v.x, v.y);
            wp[2 * q + 1] = pk2(v.z, v.w);
        }
    }
    const float cb = __ldg(ctb + lane);

    // ---- GEMM in FFMA2: y[n=t][dout=lane] = cb + sum_c pooled*ctw ----
    const ulonglong2* spv = (const ulonglong2*)s_pool[w];
#pragma unroll
    for (int t = 0; t < NB; t++) {
        unsigned long long y2 = pk2(cb, 0.f);
#pragma unroll
        for (int c4 = 0; c4 < 8; c4++) {
            // inverse of the permuted layout for j = t*32 + 4*c4
            const int idx = ((t >> 3) ? 64 : 0) + ((c4 & 1) ? 32 : 0)
                          + 4 * (t & 7) + (c4 >> 1);
            ulonglong2 pv = spv[idx];          // uniform warp-broadcast LDS.128
            y2 = ffma2(pv.x, wp[2 * c4], y2);
            y2 = ffma2(pv.y, wp[2 * c4 + 1], y2);
        }
        float lo, hi; upk2(y2, lo, hi);
        s_stage[t * 32 + lane][w] = lo + hi;
    }
    __syncthreads();

    // ---- coalesced write-out: out[row*8192 + o] = stage + bias ----
#pragma unroll
    for (int e = tid; e < NF * OB; e += 256) {
        const int row  = e >> 3;       // OB == 8
        const int col  = e & 7;
        const int oo   = o_base + col;
        const int dout = row & 31;
        out[(size_t)row * OUTNX + oo] = s_stage[row][col] + __ldg(bias + (size_t)dout * OUTNX + oo);
    }
}

extern "C" void kernel_launch(void* const* d_in, const int* in_sizes, int n_in,
                              void* d_out, int out_size) {
    const float* x    = (const float*)d_in[0];
    const void*  A    = d_in[1];
    const float* w    = (const float*)d_in[2];
    const float* mask = (const float*)d_in[3];
    const float* mw   = (const float*)d_in[4];
    const float* ctw  = (const float*)d_in[5];
    const float* ctb  = (const float*)d_in[6];
    const float* bias = (const float*)d_in[7];
    float* out = (float*)d_out;
    (void)in_sizes; (void)n_in; (void)out_size;

    dim3 pgrid(INNX / 64, NF / 64);
    dim3 pblk(32, 8);
    prep_kernel<<<pgrid, pblk>>>(x, w);

    gather_kernel<<<OUTNX / OB, 256>>>(A, mask, mw, ctw, ctb, bias, out);
}